// round 2
// baseline (speedup 1.0000x reference)
#include <cuda_runtime.h>
#include <cstdint>
#include <math.h>

#define N_ELEM 256
#define T_SEQ  32
#define H_DIM  512
#define MAXS   (N_ELEM * T_SEQ)          // worst-case executed rounds

// Broadcast buffers for hidden vectors (one slot per executed round, per layer)
__device__ float    g_h0[(size_t)MAXS * H_DIM];
__device__ float    g_h1[(size_t)MAXS * H_DIM];
__device__ unsigned g_cnt0[MAXS];        // #channels of h0[s] published
__device__ unsigned g_cnt1[MAXS];        // #channels of h1[s] published
__device__ unsigned g_abort;             // watchdog abort flag

__device__ __forceinline__ float4 ldcg4v(const float* p) {
    float4 v;
    asm volatile("ld.global.cg.v4.f32 {%0,%1,%2,%3}, [%4];"
                 : "=f"(v.x), "=f"(v.y), "=f"(v.z), "=f"(v.w)
                 : "l"(p) : "memory");
    return v;
}
__device__ __forceinline__ void stcg1(float* p, float v) {
    asm volatile("st.global.cg.f32 [%0], %1;" :: "l"(p), "f"(v) : "memory");
}
__device__ __forceinline__ unsigned ld_acq(const unsigned* p) {
    unsigned v;
    asm volatile("ld.acquire.gpu.global.u32 %0, [%1];" : "=r"(v) : "l"(p) : "memory");
    return v;
}
__device__ __forceinline__ void red_rel_add(unsigned* p, unsigned v) {
    asm volatile("red.release.gpu.global.add.u32 [%0], %1;" :: "l"(p), "r"(v) : "memory");
}
// Spin until *cnt >= target. Watchdog: after ~4M iterations raise global abort;
// any raised abort short-circuits every wait so the whole grid drains quickly.
__device__ __forceinline__ void wait_count(unsigned* cnt, unsigned target) {
    unsigned it = 0;
    while (ld_acq(cnt) < target) {
        if ((++it & 1023u) == 0u) {
            if (ld_acq(&g_abort) != 0u) return;
            if (it >= (1u << 22)) { red_rel_add(&g_abort, 1u); return; }
        }
    }
}
__device__ __forceinline__ float wsum(float v) {
    v += __shfl_xor_sync(0xffffffffu, v, 16);
    v += __shfl_xor_sync(0xffffffffu, v, 8);
    v += __shfl_xor_sync(0xffffffffu, v, 4);
    v += __shfl_xor_sync(0xffffffffu, v, 2);
    v += __shfl_xor_sync(0xffffffffu, v, 1);
    return v;
}
__device__ __forceinline__ float dot4(float4 a, float4 b) {
    return a.x * b.x + a.y * b.y + a.z * b.z + a.w * b.w;
}
__device__ __forceinline__ float sigmoidf_(float v) {
    return 1.0f / (1.0f + expf(-v));
}

// Zero counters + abort flag; optionally write dates (as float) to out.
__global__ void init_kernel(const int* __restrict__ dates, float* __restrict__ out,
                            int write_dates) {
    int idx = blockIdx.x * blockDim.x + threadIdx.x;
    if (idx < MAXS) { g_cnt0[idx] = 0u; g_cnt1[idx] = 0u; }
    if (idx == 0) g_abort = 0u;
    if (write_dates && idx < N_ELEM) out[idx] = (float)dates[idx];
}

// Persistent 2-layer pipelined GRU.
// CTAs 0..63   = group A (layer 0): x-projection + recurrence, emits h0[s].
// CTAs 64..127 = group B (layer 1): consumes h0[s], own recurrence, emits h1[s] + states.
__global__ void __launch_bounds__(256, 1)
gru_persistent(const int* __restrict__ dates, const float* __restrict__ x,
               const float* __restrict__ Wih0, const float* __restrict__ Whh0,
               const float* __restrict__ bih0, const float* __restrict__ bhh0,
               const float* __restrict__ Wih1, const float* __restrict__ Whh1,
               const float* __restrict__ bih1, const float* __restrict__ bhh1,
               float* __restrict__ out_states) {
    __shared__ int sdates[N_ELEM];
    int tid = threadIdx.x;
    if (tid < N_ELEM) sdates[tid] = dates[tid];
    __syncthreads();

    int warp = tid >> 5, lane = tid & 31;
    bool isB = (blockIdx.x >= 64);
    int cta  = isB ? (blockIdx.x - 64) : blockIdx.x;
    int c    = cta * 8 + warp;                    // owned output channel, 0..511

    const float* Wi = isB ? Wih1 : Wih0;
    const float* Wh = isB ? Whh1 : Whh0;
    const float* bi = isB ? bih1 : bih0;
    const float* bh = isB ? bhh1 : bhh0;

    // Register-resident weights: 3 gate rows (r,z,n) x 16 k-values for both matmuls.
    float4 wi[3][4], wh[3][4];
#pragma unroll
    for (int g = 0; g < 3; g++) {
        const float4* pi = reinterpret_cast<const float4*>(
            Wi + (size_t)(g * H_DIM + c) * H_DIM + lane * 16);
        const float4* ph = reinterpret_cast<const float4*>(
            Wh + (size_t)(g * H_DIM + c) * H_DIM + lane * 16);
#pragma unroll
        for (int j = 0; j < 4; j++) { wi[g][j] = pi[j]; wh[g][j] = ph[j]; }
    }
    float b_r  = bi[c] + bh[c];
    float b_z  = bi[H_DIM + c] + bh[H_DIM + c];
    float b_in = bi[2 * H_DIM + c];
    float b_hn = bh[2 * H_DIM + c];
    float hcur = 0.0f;

    float*    myH   = isB ? g_h1   : g_h0;
    unsigned* myCnt = isB ? g_cnt1 : g_cnt0;

    int s = 0;                                    // global executed-round index
    for (int n = 0; n < N_ELEM; n++) {
        bool run = (n == 0) || (sdates[n] != sdates[n - 1]);
        if (!run) {
            if (isB && lane == 0) out_states[(size_t)n * H_DIM + c] = hcur;
            continue;
        }
        for (int t = 0; t < T_SEQ; t++, s++) {
            // ---- input-side projection (gi) ----
            float4 xv[4];
            if (!isB) {
                const float4* xp = reinterpret_cast<const float4*>(
                    x + ((size_t)n * T_SEQ + t) * H_DIM + lane * 16);
#pragma unroll
                for (int j = 0; j < 4; j++) xv[j] = xp[j];
            } else {
                wait_count(&g_cnt0[s], 512u);     // layer-0 output of this round
                const float* hp = g_h0 + (size_t)s * H_DIM + lane * 16;
#pragma unroll
                for (int j = 0; j < 4; j++) xv[j] = ldcg4v(hp + j * 4);
            }
            float gr = 0.f, gz = 0.f, gn = 0.f;
#pragma unroll
            for (int j = 0; j < 4; j++) {
                gr += dot4(wi[0][j], xv[j]);
                gz += dot4(wi[1][j], xv[j]);
                gn += dot4(wi[2][j], xv[j]);
            }
            // ---- recurrent-side projection (gh) ----
            float4 hv[4];
            if (s == 0) {
                hv[0] = hv[1] = hv[2] = hv[3] = make_float4(0.f, 0.f, 0.f, 0.f);
            } else {
                wait_count(&myCnt[s - 1], 512u);
                const float* hp = myH + (size_t)(s - 1) * H_DIM + lane * 16;
#pragma unroll
                for (int j = 0; j < 4; j++) hv[j] = ldcg4v(hp + j * 4);
            }
            float hr = 0.f, hz = 0.f, hn = 0.f;
#pragma unroll
            for (int j = 0; j < 4; j++) {
                hr += dot4(wh[0][j], hv[j]);
                hz += dot4(wh[1][j], hv[j]);
                hn += dot4(wh[2][j], hv[j]);
            }
            // ---- reduce + gates + publish ----
            float ar  = wsum(gr + hr);
            float az  = wsum(gz + hz);
            float ani = wsum(gn);
            float anh = wsum(hn);
            if (lane == 0) {
                float r  = sigmoidf_(ar + b_r);
                float z  = sigmoidf_(az + b_z);
                float nn = tanhf(ani + b_in + r * (anh + b_hn));
                hcur = (1.0f - z) * nn + z * hcur;
                stcg1(myH + (size_t)s * H_DIM + c, hcur);   // data first
                red_rel_add(&myCnt[s], 1u);                 // then release-count
            }
        }
        if (isB && lane == 0) out_states[(size_t)n * H_DIM + c] = hcur;
    }
}

extern "C" void kernel_launch(void* const* d_in, const int* in_sizes, int n_in,
                              void* d_out, int out_size) {
    const int*   dates = (const int*)d_in[0];
    const float* x     = (const float*)d_in[1];
    const float* Wih0  = (const float*)d_in[2];
    const float* Whh0  = (const float*)d_in[3];
    const float* bih0  = (const float*)d_in[4];
    const float* bhh0  = (const float*)d_in[5];
    const float* Wih1  = (const float*)d_in[6];
    const float* Whh1  = (const float*)d_in[7];
    const float* bih1  = (const float*)d_in[8];
    const float* bhh1  = (const float*)d_in[9];
    float* out = (float*)d_out;

    // Reference returns (dates, states); if out_size includes the extra N
    // elements, dates (cast to float) come first.
    int with_dates = (out_size >= N_ELEM + N_ELEM * H_DIM) ? 1 : 0;
    float* states = out + (with_dates ? N_ELEM : 0);

    init_kernel<<<(MAXS + 255) / 256, 256>>>(dates, out, with_dates);
    gru_persistent<<<128, 256>>>(dates, x, Wih0, Whh0, bih0, bhh0,
                                 Wih1, Whh1, bih1, bhh1, states);
}